// round 10
// baseline (speedup 1.0000x reference)
#include <cuda_runtime.h>
#include <cuda_bf16.h>
#include <cstdint>

#define IN_F 128
#define OUT_F 64
#define MAX_N 100000
#define MAX_E 1600000
#define ALPHAF 10.0f

typedef unsigned long long ull;

// Scratch (allocation-free rule: __device__ globals)
__device__ int      g_cnt[MAX_N];        // per-dst in-degree counts
__device__ int      g_rowstart[MAX_N];   // CSR row offsets
__device__ int      g_rank[MAX_E];       // per-edge rank within its dst node
__device__ float    g_deg[MAX_N];        // sum of incoming edge weights
__device__ unsigned g_h16[(size_t)MAX_N * (OUT_F / 2)];  // h rows in bf16x2 words
__device__ unsigned g_epack[MAX_E];      // packed edge: src | (etype<<17)
// decoupled-lookback scan state
__device__ volatile int g_scanflag[64];  // 0=invalid 1=aggregate 2=inclusive
__device__ volatile int g_scanagg[64];
__device__ volatile int g_scaninc[64];

// ---------------------------------------------------------------------------
// K1: zero counters + deg + scan flags
// ---------------------------------------------------------------------------
__global__ void zero_kernel(int n) {
    int i = blockIdx.x * blockDim.x + threadIdx.x;
    if (i < n) { g_cnt[i] = 0; g_deg[i] = 0.0f; }
    if (blockIdx.x == 0 && threadIdx.x < 64) g_scanflag[threadIdx.x] = 0;
}

// ---------------------------------------------------------------------------
// K2: histogram of dst + per-edge rank capture + fused deg accumulation
// ---------------------------------------------------------------------------
__global__ void hist_kernel(const int* __restrict__ dst,
                            const int* __restrict__ efeat,
                            const float* __restrict__ edge_weight,
                            int E) {
    int e = blockIdx.x * blockDim.x + threadIdx.x;
    if (e >= E) return;
    int d = dst[e];
    float w = __ldg(&edge_weight[efeat[e] - 1]) * ALPHAF;
    w = (w > 0.0f) ? w : 0.01f * w;
    int r = atomicAdd(&g_cnt[d], 1);
    g_rank[e] = r;
    atomicAdd(&g_deg[d], w);
}

// ---------------------------------------------------------------------------
// K3: single-pass exclusive scan of g_cnt -> g_rowstart (decoupled lookback).
// ---------------------------------------------------------------------------
__global__ __launch_bounds__(256) void scan_kernel(int n) {
    __shared__ int s[256];
    __shared__ int s_off;
    const int tid = threadIdx.x;
    const int b = blockIdx.x;
    const int base = b * 2048 + tid * 8;

    int v[8];
    int tsum = 0;
    #pragma unroll
    for (int j = 0; j < 8; j++) {
        int idx = base + j;
        int c = (idx < n) ? g_cnt[idx] : 0;
        v[j] = tsum;
        tsum += c;
    }
    s[tid] = tsum;
    __syncthreads();
    #pragma unroll
    for (int off = 1; off < 256; off <<= 1) {
        int t = 0;
        if (tid >= off) t = s[tid - off];
        __syncthreads();
        if (tid >= off) s[tid] += t;
        __syncthreads();
    }
    int texcl = s[tid] - tsum;
    int total = s[255];

    if (tid == 0) {
        if (b == 0) {
            g_scaninc[0] = total;
            __threadfence();
            g_scanflag[0] = 2;
            s_off = 0;
        } else {
            g_scanagg[b] = total;
            __threadfence();
            g_scanflag[b] = 1;
            int run = 0;
            int p = b - 1;
            while (true) {
                int f = g_scanflag[p];
                if (f == 2) { __threadfence(); run += g_scaninc[p]; break; }
                if (f == 1) { __threadfence(); run += g_scanagg[p]; p--; }
            }
            g_scaninc[b] = run + total;
            __threadfence();
            g_scanflag[b] = 2;
            s_off = run;
        }
    }
    __syncthreads();
    int off = s_off;

    #pragma unroll
    for (int j = 0; j < 8; j++) {
        int idx = base + j;
        if (idx < n) g_rowstart[idx] = off + texcl + v[j];
    }
}

// ---------------------------------------------------------------------------
// K4: scatter packed edges into CSR slots — NO atomics (rank precomputed)
// ---------------------------------------------------------------------------
__global__ void scatter_kernel(const int* __restrict__ src,
                               const int* __restrict__ dst,
                               const int* __restrict__ efeat,
                               int E) {
    int e = blockIdx.x * blockDim.x + threadIdx.x;
    if (e >= E) return;
    int d = dst[e];
    int p = g_rowstart[d] + g_rank[e];
    g_epack[p] = (unsigned)src[e] | ((unsigned)(efeat[e] - 1) << 17);
}

// ---------------------------------------------------------------------------
// K5: GEMM with packed fp32x2 FFMA (2x fp32 FMA throughput).
// fr = feat @ weight ; out = fr + bias ; g_h16 = bf16(fr/max(deg,1))
// sA2 holds splat pairs (a,a) so the inner loop needs no packing MOVs.
// ---------------------------------------------------------------------------
__global__ __launch_bounds__(256) void gemm_kernel(
    const float* __restrict__ feat,
    const float* __restrict__ weight,
    const float* __restrict__ bias,
    float* __restrict__ out,
    int n)
{
    __shared__ ull   sA2[64][IN_F];      // 64KB: (a,a) splat per element
    __shared__ float sB[IN_F][OUT_F];    // 32KB

    const int tid = threadIdx.y * 16 + threadIdx.x;
    const int rowBase = blockIdx.x * 64;

    // Fill A tile as splat pairs: 64x128 elems = 2048 float4 loads
    #pragma unroll
    for (int it = 0; it < 8; it++) {
        int idx = tid + it * 256;
        int r = idx >> 5;
        int c4 = idx & 31;
        float4 v = make_float4(0.f, 0.f, 0.f, 0.f);
        int gr = rowBase + r;
        if (gr < n)
            v = reinterpret_cast<const float4*>(feat)[(size_t)gr * (IN_F / 4) + c4];
        ull s0, s1, s2, s3;
        asm("mov.b64 %0, {%1, %1};" : "=l"(s0) : "f"(v.x));
        asm("mov.b64 %0, {%1, %1};" : "=l"(s1) : "f"(v.y));
        asm("mov.b64 %0, {%1, %1};" : "=l"(s2) : "f"(v.z));
        asm("mov.b64 %0, {%1, %1};" : "=l"(s3) : "f"(v.w));
        sA2[r][c4 * 4 + 0] = s0;
        sA2[r][c4 * 4 + 1] = s1;
        sA2[r][c4 * 4 + 2] = s2;
        sA2[r][c4 * 4 + 3] = s3;
    }
    // Fill B tile
    #pragma unroll
    for (int it = 0; it < 8; it++) {
        int idx = tid + it * 256;
        int r = idx >> 4;
        int c4 = idx & 15;
        float4 v = reinterpret_cast<const float4*>(weight)[(size_t)r * (OUT_F / 4) + c4];
        *reinterpret_cast<float4*>(&sB[r][c4 * 4]) = v;
    }
    __syncthreads();

    const int ty4 = threadIdx.y * 4;
    const int tx4 = threadIdx.x * 4;

    // acc pairs over columns: accP[i][0] = (c[tx4], c[tx4+1]), accP[i][1] = (c[tx4+2], c[tx4+3])
    ull accP[4][2];
    #pragma unroll
    for (int i = 0; i < 4; i++) { accP[i][0] = 0ULL; accP[i][1] = 0ULL; }

    #pragma unroll 4
    for (int k = 0; k < IN_F; k++) {
        ull a0 = sA2[ty4 + 0][k];
        ull a1 = sA2[ty4 + 1][k];
        ull a2 = sA2[ty4 + 2][k];
        ull a3 = sA2[ty4 + 3][k];
        const ull* bp = reinterpret_cast<const ull*>(&sB[k][tx4]);
        ull b01 = bp[0];
        ull b23 = bp[1];
        asm("fma.rn.f32x2 %0, %1, %2, %0;" : "+l"(accP[0][0]) : "l"(a0), "l"(b01));
        asm("fma.rn.f32x2 %0, %1, %2, %0;" : "+l"(accP[0][1]) : "l"(a0), "l"(b23));
        asm("fma.rn.f32x2 %0, %1, %2, %0;" : "+l"(accP[1][0]) : "l"(a1), "l"(b01));
        asm("fma.rn.f32x2 %0, %1, %2, %0;" : "+l"(accP[1][1]) : "l"(a1), "l"(b23));
        asm("fma.rn.f32x2 %0, %1, %2, %0;" : "+l"(accP[2][0]) : "l"(a2), "l"(b01));
        asm("fma.rn.f32x2 %0, %1, %2, %0;" : "+l"(accP[2][1]) : "l"(a2), "l"(b23));
        asm("fma.rn.f32x2 %0, %1, %2, %0;" : "+l"(accP[3][0]) : "l"(a3), "l"(b01));
        asm("fma.rn.f32x2 %0, %1, %2, %0;" : "+l"(accP[3][1]) : "l"(a3), "l"(b23));
    }

    float4 bi = *reinterpret_cast<const float4*>(&bias[tx4]);

    #pragma unroll
    for (int i = 0; i < 4; i++) {
        int gr = rowBase + ty4 + i;
        if (gr >= n) break;
        float d = g_deg[gr];
        float norm = 1.0f / fmaxf(d, 1.0f);
        float fx, fy, fz, fw;
        asm("mov.b64 {%0, %1}, %2;" : "=f"(fx), "=f"(fy) : "l"(accP[i][0]));
        asm("mov.b64 {%0, %1}, %2;" : "=f"(fz), "=f"(fw) : "l"(accP[i][1]));
        float4 o = make_float4(fx + bi.x, fy + bi.y, fz + bi.z, fw + bi.w);
        reinterpret_cast<float4*>(out)[(size_t)gr * (OUT_F / 4) + (tx4 >> 2)] = o;

        __nv_bfloat162 p0 = __floats2bfloat162_rn(fx * norm, fy * norm);
        __nv_bfloat162 p1 = __floats2bfloat162_rn(fz * norm, fw * norm);
        uint2 u;
        u.x = *reinterpret_cast<unsigned*>(&p0);
        u.y = *reinterpret_cast<unsigned*>(&p1);
        *reinterpret_cast<uint2*>(&g_h16[(size_t)gr * (OUT_F / 2) + (tx4 >> 1)]) = u;
    }
}

// ---------------------------------------------------------------------------
// K6: pull-gather. 8 threads per dst node; uint4 (16B) per lane; unroll x4
// ---------------------------------------------------------------------------
__global__ __launch_bounds__(256) void gather_kernel(
    float* __restrict__ out,
    const float* __restrict__ edge_weight,
    int n)
{
    __shared__ float s_wl[8];
    if (threadIdx.x < 8) {
        float w = edge_weight[threadIdx.x] * ALPHAF;
        s_wl[threadIdx.x] = (w > 0.0f) ? w : 0.01f * w;
    }
    __syncthreads();

    int node = blockIdx.x * 32 + (threadIdx.x >> 3);
    int lane = threadIdx.x & 7;
    if (node >= n) return;

    const int st = g_rowstart[node];
    const int cnt = g_cnt[node];

    float acc[8];
    #pragma unroll
    for (int j = 0; j < 8; j++) acc[j] = 0.0f;

    const uint4* __restrict__ hp = reinterpret_cast<const uint4*>(g_h16);

    int i = 0;
    for (; i + 4 <= cnt; i += 4) {
        unsigned e0 = g_epack[st + i + 0];
        unsigned e1 = g_epack[st + i + 1];
        unsigned e2 = g_epack[st + i + 2];
        unsigned e3 = g_epack[st + i + 3];
        uint4 h0 = hp[(size_t)(e0 & 0x1FFFFu) * 8 + lane];
        uint4 h1 = hp[(size_t)(e1 & 0x1FFFFu) * 8 + lane];
        uint4 h2 = hp[(size_t)(e2 & 0x1FFFFu) * 8 + lane];
        uint4 h3 = hp[(size_t)(e3 & 0x1FFFFu) * 8 + lane];
        float w0 = s_wl[e0 >> 17];
        float w1 = s_wl[e1 >> 17];
        float w2 = s_wl[e2 >> 17];
        float w3 = s_wl[e3 >> 17];
        const __nv_bfloat162* b0 = reinterpret_cast<const __nv_bfloat162*>(&h0);
        const __nv_bfloat162* b1 = reinterpret_cast<const __nv_bfloat162*>(&h1);
        const __nv_bfloat162* b2 = reinterpret_cast<const __nv_bfloat162*>(&h2);
        const __nv_bfloat162* b3 = reinterpret_cast<const __nv_bfloat162*>(&h3);
        #pragma unroll
        for (int j = 0; j < 4; j++) {
            float2 f0 = __bfloat1622float2(b0[j]);
            float2 f1 = __bfloat1622float2(b1[j]);
            float2 f2 = __bfloat1622float2(b2[j]);
            float2 f3 = __bfloat1622float2(b3[j]);
            acc[2 * j + 0] += f0.x * w0 + f1.x * w1 + f2.x * w2 + f3.x * w3;
            acc[2 * j + 1] += f0.y * w0 + f1.y * w1 + f2.y * w2 + f3.y * w3;
        }
    }
    for (; i < cnt; i++) {
        unsigned e0 = g_epack[st + i];
        uint4 h0 = hp[(size_t)(e0 & 0x1FFFFu) * 8 + lane];
        float w0 = s_wl[e0 >> 17];
        const __nv_bfloat162* b0 = reinterpret_cast<const __nv_bfloat162*>(&h0);
        #pragma unroll
        for (int j = 0; j < 4; j++) {
            float2 f0 = __bfloat1622float2(b0[j]);
            acc[2 * j + 0] += f0.x * w0;
            acc[2 * j + 1] += f0.y * w0;
        }
    }

    float4* op = reinterpret_cast<float4*>(out + (size_t)node * OUT_F + lane * 8);
    float4 a = op[0];
    float4 b = op[1];
    a.x += acc[0]; a.y += acc[1]; a.z += acc[2]; a.w += acc[3];
    b.x += acc[4]; b.y += acc[5]; b.z += acc[6]; b.w += acc[7];
    op[0] = a;
    op[1] = b;
}

// ---------------------------------------------------------------------------
// Launch
// ---------------------------------------------------------------------------
extern "C" void kernel_launch(void* const* d_in, const int* in_sizes, int n_in,
                              void* d_out, int out_size) {
    const float* feat        = (const float*)d_in[0];
    const float* edge_weight = (const float*)d_in[1];
    const float* weight      = (const float*)d_in[2];
    const float* bias        = (const float*)d_in[3];
    const int*   src         = (const int*)d_in[4];
    const int*   dst         = (const int*)d_in[5];
    const int*   efeat       = (const int*)d_in[6];
    float* out = (float*)d_out;

    int n = in_sizes[0] / IN_F;
    int E = in_sizes[4];
    int nb = (n + 2047) / 2048;

    zero_kernel<<<(n + 255) / 256, 256>>>(n);
    hist_kernel<<<(E + 255) / 256, 256>>>(dst, efeat, edge_weight, E);
    scan_kernel<<<nb, 256>>>(n);
    scatter_kernel<<<(E + 255) / 256, 256>>>(src, dst, efeat, E);

    dim3 gblk(16, 16);
    gemm_kernel<<<(n + 63) / 64, gblk>>>(feat, weight, bias, out, n);

    gather_kernel<<<(n + 31) / 32, 256>>>(out, edge_weight, n);
}

// round 11
// speedup vs baseline: 1.0369x; 1.0369x over previous
#include <cuda_runtime.h>
#include <cuda_bf16.h>
#include <cstdint>

#define IN_F 128
#define OUT_F 64
#define MAX_N 100000
#define MAX_E 1600000
#define ALPHAF 10.0f

// Scratch (allocation-free rule: __device__ globals)
__device__ int      g_cnt[MAX_N];        // per-dst in-degree counts
__device__ int      g_rowstart[MAX_N];   // CSR row offsets
__device__ int      g_cursor[MAX_N];     // scatter cursors
__device__ float    g_deg[MAX_N];        // sum of incoming edge weights
__device__ unsigned g_h16[(size_t)MAX_N * (OUT_F / 2)];  // h rows in bf16x2 words
__device__ unsigned g_epack[MAX_E];      // packed edge: src | (etype<<17)
// decoupled-lookback scan state
__device__ volatile int g_scanflag[64];  // 0=invalid 1=aggregate 2=inclusive
__device__ volatile int g_scanagg[64];
__device__ volatile int g_scaninc[64];

// ---------------------------------------------------------------------------
// K1: zero counters + deg + scan flags
// ---------------------------------------------------------------------------
__global__ void zero_kernel(int n) {
    int i = blockIdx.x * blockDim.x + threadIdx.x;
    if (i < n) { g_cnt[i] = 0; g_deg[i] = 0.0f; }
    if (blockIdx.x == 0 && threadIdx.x < 64) g_scanflag[threadIdx.x] = 0;
}

// ---------------------------------------------------------------------------
// K2: histogram of dst + fused deg accumulation.
// Both atomicAdd returns UNUSED -> ptxas emits REDG (no round-trip).
// ---------------------------------------------------------------------------
__global__ void hist_kernel(const int* __restrict__ dst,
                            const int* __restrict__ efeat,
                            const float* __restrict__ edge_weight,
                            int E) {
    int e = blockIdx.x * blockDim.x + threadIdx.x;
    if (e >= E) return;
    int d = dst[e];
    float w = __ldg(&edge_weight[efeat[e] - 1]) * ALPHAF;
    w = (w > 0.0f) ? w : 0.01f * w;
    atomicAdd(&g_cnt[d], 1);
    atomicAdd(&g_deg[d], w);
}

// ---------------------------------------------------------------------------
// K3: single-pass exclusive scan of g_cnt -> g_rowstart AND g_cursor
// (decoupled lookback; <=49 blocks, all resident in wave 1)
// ---------------------------------------------------------------------------
__global__ __launch_bounds__(256) void scan_kernel(int n) {
    __shared__ int s[256];
    __shared__ int s_off;
    const int tid = threadIdx.x;
    const int b = blockIdx.x;
    const int base = b * 2048 + tid * 8;

    int v[8];
    int tsum = 0;
    #pragma unroll
    for (int j = 0; j < 8; j++) {
        int idx = base + j;
        int c = (idx < n) ? g_cnt[idx] : 0;
        v[j] = tsum;
        tsum += c;
    }
    s[tid] = tsum;
    __syncthreads();
    #pragma unroll
    for (int off = 1; off < 256; off <<= 1) {
        int t = 0;
        if (tid >= off) t = s[tid - off];
        __syncthreads();
        if (tid >= off) s[tid] += t;
        __syncthreads();
    }
    int texcl = s[tid] - tsum;        // exclusive prefix of this thread's sum
    int total = s[255];               // block total

    if (tid == 0) {
        if (b == 0) {
            g_scaninc[0] = total;
            __threadfence();
            g_scanflag[0] = 2;
            s_off = 0;
        } else {
            g_scanagg[b] = total;
            __threadfence();
            g_scanflag[b] = 1;
            int run = 0;
            int p = b - 1;
            while (true) {
                int f = g_scanflag[p];
                if (f == 2) { __threadfence(); run += g_scaninc[p]; break; }
                if (f == 1) { __threadfence(); run += g_scanagg[p]; p--; }
            }
            g_scaninc[b] = run + total;
            __threadfence();
            g_scanflag[b] = 2;
            s_off = run;
        }
    }
    __syncthreads();
    int off = s_off;

    #pragma unroll
    for (int j = 0; j < 8; j++) {
        int idx = base + j;
        if (idx < n) {
            int r = off + texcl + v[j];
            g_rowstart[idx] = r;
            g_cursor[idx] = r;
        }
    }
}

// ---------------------------------------------------------------------------
// K4: scatter packed edges into CSR slots (cursor atomic)
// ---------------------------------------------------------------------------
__global__ void scatter_kernel(const int* __restrict__ src,
                               const int* __restrict__ dst,
                               const int* __restrict__ efeat,
                               int E) {
    int e = blockIdx.x * blockDim.x + threadIdx.x;
    if (e >= E) return;
    int d = dst[e];
    int p = atomicAdd(&g_cursor[d], 1);
    g_epack[p] = (unsigned)src[e] | ((unsigned)(efeat[e] - 1) << 17);
}

// ---------------------------------------------------------------------------
// K5: GEMM  fr = feat @ weight ;  out = fr + bias ;  g_h16 = bf16(fr/max(deg,1))
// (plain fp32 version — the 136.6us best's GEMM)
// ---------------------------------------------------------------------------
__global__ __launch_bounds__(256) void gemm_kernel(
    const float* __restrict__ feat,
    const float* __restrict__ weight,
    const float* __restrict__ bias,
    float* __restrict__ out,
    int n)
{
    __shared__ float sA[64][IN_F + 1];
    __shared__ float sB[IN_F][OUT_F];

    const int tid = threadIdx.y * 16 + threadIdx.x;
    const int rowBase = blockIdx.x * 64;

    #pragma unroll
    for (int it = 0; it < 8; it++) {
        int idx = tid + it * 256;
        int r = idx >> 5;
        int c4 = idx & 31;
        float4 v = make_float4(0.f, 0.f, 0.f, 0.f);
        int gr = rowBase + r;
        if (gr < n)
            v = reinterpret_cast<const float4*>(feat)[(size_t)gr * (IN_F / 4) + c4];
        sA[r][c4 * 4 + 0] = v.x;
        sA[r][c4 * 4 + 1] = v.y;
        sA[r][c4 * 4 + 2] = v.z;
        sA[r][c4 * 4 + 3] = v.w;
    }
    #pragma unroll
    for (int it = 0; it < 8; it++) {
        int idx = tid + it * 256;
        int r = idx >> 4;
        int c4 = idx & 15;
        float4 v = reinterpret_cast<const float4*>(weight)[(size_t)r * (OUT_F / 4) + c4];
        *reinterpret_cast<float4*>(&sB[r][c4 * 4]) = v;
    }
    __syncthreads();

    float acc[4][4];
    #pragma unroll
    for (int i = 0; i < 4; i++)
        #pragma unroll
        for (int j = 0; j < 4; j++) acc[i][j] = 0.0f;

    const int ty4 = threadIdx.y * 4;
    const int tx4 = threadIdx.x * 4;

    #pragma unroll 4
    for (int k = 0; k < IN_F; k++) {
        float a0 = sA[ty4 + 0][k];
        float a1 = sA[ty4 + 1][k];
        float a2 = sA[ty4 + 2][k];
        float a3 = sA[ty4 + 3][k];
        float4 b = *reinterpret_cast<const float4*>(&sB[k][tx4]);
        acc[0][0] += a0 * b.x; acc[0][1] += a0 * b.y; acc[0][2] += a0 * b.z; acc[0][3] += a0 * b.w;
        acc[1][0] += a1 * b.x; acc[1][1] += a1 * b.y; acc[1][2] += a1 * b.z; acc[1][3] += a1 * b.w;
        acc[2][0] += a2 * b.x; acc[2][1] += a2 * b.y; acc[2][2] += a2 * b.z; acc[2][3] += a2 * b.w;
        acc[3][0] += a3 * b.x; acc[3][1] += a3 * b.y; acc[3][2] += a3 * b.z; acc[3][3] += a3 * b.w;
    }

    float4 bi = *reinterpret_cast<const float4*>(&bias[tx4]);

    #pragma unroll
    for (int i = 0; i < 4; i++) {
        int gr = rowBase + ty4 + i;
        if (gr >= n) break;
        float d = g_deg[gr];
        float norm = 1.0f / fmaxf(d, 1.0f);
        float4 fr = make_float4(acc[i][0], acc[i][1], acc[i][2], acc[i][3]);
        float4 o  = make_float4(fr.x + bi.x, fr.y + bi.y, fr.z + bi.z, fr.w + bi.w);
        reinterpret_cast<float4*>(out)[(size_t)gr * (OUT_F / 4) + (tx4 >> 2)] = o;

        __nv_bfloat162 p0 = __floats2bfloat162_rn(fr.x * norm, fr.y * norm);
        __nv_bfloat162 p1 = __floats2bfloat162_rn(fr.z * norm, fr.w * norm);
        uint2 u;
        u.x = *reinterpret_cast<unsigned*>(&p0);
        u.y = *reinterpret_cast<unsigned*>(&p1);
        *reinterpret_cast<uint2*>(&g_h16[(size_t)gr * (OUT_F / 2) + (tx4 >> 1)]) = u;
    }
}

// ---------------------------------------------------------------------------
// K6: pull-gather. 8 threads per dst node; uint4 (16B) per lane; unroll x4
// ---------------------------------------------------------------------------
__global__ __launch_bounds__(256) void gather_kernel(
    float* __restrict__ out,
    const float* __restrict__ edge_weight,
    int n)
{
    __shared__ float s_wl[8];
    if (threadIdx.x < 8) {
        float w = edge_weight[threadIdx.x] * ALPHAF;
        s_wl[threadIdx.x] = (w > 0.0f) ? w : 0.01f * w;
    }
    __syncthreads();

    int node = blockIdx.x * 32 + (threadIdx.x >> 3);
    int lane = threadIdx.x & 7;
    if (node >= n) return;

    const int st = g_rowstart[node];
    const int cnt = g_cnt[node];

    float acc[8];
    #pragma unroll
    for (int j = 0; j < 8; j++) acc[j] = 0.0f;

    const uint4* __restrict__ hp = reinterpret_cast<const uint4*>(g_h16);

    int i = 0;
    for (; i + 4 <= cnt; i += 4) {
        unsigned e0 = g_epack[st + i + 0];
        unsigned e1 = g_epack[st + i + 1];
        unsigned e2 = g_epack[st + i + 2];
        unsigned e3 = g_epack[st + i + 3];
        uint4 h0 = hp[(size_t)(e0 & 0x1FFFFu) * 8 + lane];
        uint4 h1 = hp[(size_t)(e1 & 0x1FFFFu) * 8 + lane];
        uint4 h2 = hp[(size_t)(e2 & 0x1FFFFu) * 8 + lane];
        uint4 h3 = hp[(size_t)(e3 & 0x1FFFFu) * 8 + lane];
        float w0 = s_wl[e0 >> 17];
        float w1 = s_wl[e1 >> 17];
        float w2 = s_wl[e2 >> 17];
        float w3 = s_wl[e3 >> 17];
        const __nv_bfloat162* b0 = reinterpret_cast<const __nv_bfloat162*>(&h0);
        const __nv_bfloat162* b1 = reinterpret_cast<const __nv_bfloat162*>(&h1);
        const __nv_bfloat162* b2 = reinterpret_cast<const __nv_bfloat162*>(&h2);
        const __nv_bfloat162* b3 = reinterpret_cast<const __nv_bfloat162*>(&h3);
        #pragma unroll
        for (int j = 0; j < 4; j++) {
            float2 f0 = __bfloat1622float2(b0[j]);
            float2 f1 = __bfloat1622float2(b1[j]);
            float2 f2 = __bfloat1622float2(b2[j]);
            float2 f3 = __bfloat1622float2(b3[j]);
            acc[2 * j + 0] += f0.x * w0 + f1.x * w1 + f2.x * w2 + f3.x * w3;
            acc[2 * j + 1] += f0.y * w0 + f1.y * w1 + f2.y * w2 + f3.y * w3;
        }
    }
    for (; i < cnt; i++) {
        unsigned e0 = g_epack[st + i];
        uint4 h0 = hp[(size_t)(e0 & 0x1FFFFu) * 8 + lane];
        float w0 = s_wl[e0 >> 17];
        const __nv_bfloat162* b0 = reinterpret_cast<const __nv_bfloat162*>(&h0);
        #pragma unroll
        for (int j = 0; j < 4; j++) {
            float2 f0 = __bfloat1622float2(b0[j]);
            acc[2 * j + 0] += f0.x * w0;
            acc[2 * j + 1] += f0.y * w0;
        }
    }

    float4* op = reinterpret_cast<float4*>(out + (size_t)node * OUT_F + lane * 8);
    float4 a = op[0];
    float4 b = op[1];
    a.x += acc[0]; a.y += acc[1]; a.z += acc[2]; a.w += acc[3];
    b.x += acc[4]; b.y += acc[5]; b.z += acc[6]; b.w += acc[7];
    op[0] = a;
    op[1] = b;
}

// ---------------------------------------------------------------------------
// Launch
// ---------------------------------------------------------------------------
extern "C" void kernel_launch(void* const* d_in, const int* in_sizes, int n_in,
                              void* d_out, int out_size) {
    const float* feat        = (const float*)d_in[0];
    const float* edge_weight = (const float*)d_in[1];
    const float* weight      = (const float*)d_in[2];
    const float* bias        = (const float*)d_in[3];
    const int*   src         = (const int*)d_in[4];
    const int*   dst         = (const int*)d_in[5];
    const int*   efeat       = (const int*)d_in[6];
    float* out = (float*)d_out;

    int n = in_sizes[0] / IN_F;
    int E = in_sizes[4];
    int nb = (n + 2047) / 2048;

    zero_kernel<<<(n + 255) / 256, 256>>>(n);
    hist_kernel<<<(E + 255) / 256, 256>>>(dst, efeat, edge_weight, E);
    scan_kernel<<<nb, 256>>>(n);
    scatter_kernel<<<(E + 255) / 256, 256>>>(src, dst, efeat, E);

    dim3 gblk(16, 16);
    gemm_kernel<<<(n + 63) / 64, gblk>>>(feat, weight, bias, out, n);

    gather_kernel<<<(n + 31) / 32, 256>>>(out, edge_weight, n);
}

// round 13
// speedup vs baseline: 1.0996x; 1.0604x over previous
#include <cuda_runtime.h>
#include <cuda_bf16.h>
#include <cstdint>

#define IN_F 128
#define OUT_F 64
#define MAX_N 100000
#define MAX_E 1600000
#define ALPHAF 10.0f

// Scratch (allocation-free rule: __device__ globals)
__device__ int      g_cnt[MAX_N];        // per-dst in-degree counts
__device__ int      g_rowstart[MAX_N];   // CSR row offsets
__device__ int      g_cursor[MAX_N];     // scatter cursors
__device__ float    g_deg[MAX_N];        // sum of incoming edge weights
__device__ unsigned g_h16[(size_t)MAX_N * (OUT_F / 2)];  // h rows in bf16x2 words
__device__ unsigned g_epack[MAX_E];      // packed edge: src | (etype<<17)
// scan state: per-block aggregate + publish flag
__device__ volatile int g_scanflag[64];
__device__ volatile int g_scanagg[64];

// ---------------------------------------------------------------------------
// K1: zero counters + deg + scan flags
// ---------------------------------------------------------------------------
__global__ void zero_kernel(int n) {
    int i = blockIdx.x * blockDim.x + threadIdx.x;
    if (i < n) { g_cnt[i] = 0; g_deg[i] = 0.0f; }
    if (blockIdx.x == 0 && threadIdx.x < 64) g_scanflag[threadIdx.x] = 0;
}

// ---------------------------------------------------------------------------
// K2: histogram of dst + fused deg accumulation. 2 edges/thread (MLP=2).
// Both atomicAdd returns UNUSED -> REDG (no round-trip).
// ---------------------------------------------------------------------------
__global__ void hist_kernel(const int* __restrict__ dst,
                            const int* __restrict__ efeat,
                            const float* __restrict__ edge_weight,
                            int E) {
    int e = (blockIdx.x * blockDim.x + threadIdx.x) * 2;
    if (e + 1 < E) {
        int2 d2 = *reinterpret_cast<const int2*>(dst + e);
        int2 t2 = *reinterpret_cast<const int2*>(efeat + e);
        float w0 = __ldg(&edge_weight[t2.x - 1]) * ALPHAF;
        float w1 = __ldg(&edge_weight[t2.y - 1]) * ALPHAF;
        w0 = (w0 > 0.0f) ? w0 : 0.01f * w0;
        w1 = (w1 > 0.0f) ? w1 : 0.01f * w1;
        atomicAdd(&g_cnt[d2.x], 1);
        atomicAdd(&g_cnt[d2.y], 1);
        atomicAdd(&g_deg[d2.x], w0);
        atomicAdd(&g_deg[d2.y], w1);
    } else if (e < E) {
        int d = dst[e];
        float w = __ldg(&edge_weight[efeat[e] - 1]) * ALPHAF;
        w = (w > 0.0f) ? w : 0.01f * w;
        atomicAdd(&g_cnt[d], 1);
        atomicAdd(&g_deg[d], w);
    }
}

// ---------------------------------------------------------------------------
// K3: single-pass exclusive scan of g_cnt -> g_rowstart AND g_cursor.
// All blocks resident (<=49 on 148 SMs): each block publishes its aggregate,
// then warp 0 reads ALL predecessor aggregates in parallel (no serial chain).
// ---------------------------------------------------------------------------
__global__ __launch_bounds__(256) void scan_kernel(int n) {
    __shared__ int s[256];
    __shared__ int s_off;
    const int tid = threadIdx.x;
    const int b = blockIdx.x;
    const int base = b * 2048 + tid * 8;

    int v[8];
    int tsum = 0;
    #pragma unroll
    for (int j = 0; j < 8; j++) {
        int idx = base + j;
        int c = (idx < n) ? g_cnt[idx] : 0;
        v[j] = tsum;
        tsum += c;
    }
    s[tid] = tsum;
    __syncthreads();
    #pragma unroll
    for (int off = 1; off < 256; off <<= 1) {
        int t = 0;
        if (tid >= off) t = s[tid - off];
        __syncthreads();
        if (tid >= off) s[tid] += t;
        __syncthreads();
    }
    int texcl = s[tid] - tsum;        // exclusive prefix of this thread's sum
    int total = s[255];               // block total

    // publish this block's aggregate
    if (tid == 0) {
        s_off = 0;
        g_scanagg[b] = total;
        __threadfence();
        g_scanflag[b] = 1;
    }
    __syncthreads();

    // warp 0: sum ALL predecessor aggregates in parallel
    if (tid < 32 && b > 0) {
        int run = 0;
        for (int base2 = 0; base2 < b; base2 += 32) {
            int p = base2 + tid;
            int val = 0;
            if (p < b) {
                while (g_scanflag[p] == 0) { }
                __threadfence();
                val = g_scanagg[p];
            }
            #pragma unroll
            for (int o = 16; o; o >>= 1)
                val += __shfl_down_sync(0xffffffffu, val, o);
            if (tid == 0) run += val;
        }
        if (tid == 0) s_off = run;
    }
    __syncthreads();
    int off = s_off;

    #pragma unroll
    for (int j = 0; j < 8; j++) {
        int idx = base + j;
        if (idx < n) {
            int r = off + texcl + v[j];
            g_rowstart[idx] = r;
            g_cursor[idx] = r;
        }
    }
}

// ---------------------------------------------------------------------------
// K4: scatter packed edges into CSR slots (cursor atomic). 2 edges/thread.
// ---------------------------------------------------------------------------
__global__ void scatter_kernel(const int* __restrict__ src,
                               const int* __restrict__ dst,
                               const int* __restrict__ efeat,
                               int E) {
    int e = (blockIdx.x * blockDim.x + threadIdx.x) * 2;
    if (e + 1 < E) {
        int2 s2 = *reinterpret_cast<const int2*>(src + e);
        int2 d2 = *reinterpret_cast<const int2*>(dst + e);
        int2 t2 = *reinterpret_cast<const int2*>(efeat + e);
        int p0 = atomicAdd(&g_cursor[d2.x], 1);
        int p1 = atomicAdd(&g_cursor[d2.y], 1);
        g_epack[p0] = (unsigned)s2.x | ((unsigned)(t2.x - 1) << 17);
        g_epack[p1] = (unsigned)s2.y | ((unsigned)(t2.y - 1) << 17);
    } else if (e < E) {
        int d = dst[e];
        int p = atomicAdd(&g_cursor[d], 1);
        g_epack[p] = (unsigned)src[e] | ((unsigned)(efeat[e] - 1) << 17);
    }
}

// ---------------------------------------------------------------------------
// K5: GEMM  fr = feat @ weight ;  out = fr + bias ;  g_h16 = bf16(fr/max(deg,1))
// ---------------------------------------------------------------------------
__global__ __launch_bounds__(256) void gemm_kernel(
    const float* __restrict__ feat,
    const float* __restrict__ weight,
    const float* __restrict__ bias,
    float* __restrict__ out,
    int n)
{
    __shared__ float sA[64][IN_F + 1];
    __shared__ float sB[IN_F][OUT_F];

    const int tid = threadIdx.y * 16 + threadIdx.x;
    const int rowBase = blockIdx.x * 64;

    #pragma unroll
    for (int it = 0; it < 8; it++) {
        int idx = tid + it * 256;
        int r = idx >> 5;
        int c4 = idx & 31;
        float4 v = make_float4(0.f, 0.f, 0.f, 0.f);
        int gr = rowBase + r;
        if (gr < n)
            v = reinterpret_cast<const float4*>(feat)[(size_t)gr * (IN_F / 4) + c4];
        sA[r][c4 * 4 + 0] = v.x;
        sA[r][c4 * 4 + 1] = v.y;
        sA[r][c4 * 4 + 2] = v.z;
        sA[r][c4 * 4 + 3] = v.w;
    }
    #pragma unroll
    for (int it = 0; it < 8; it++) {
        int idx = tid + it * 256;
        int r = idx >> 4;
        int c4 = idx & 15;
        float4 v = reinterpret_cast<const float4*>(weight)[(size_t)r * (OUT_F / 4) + c4];
        *reinterpret_cast<float4*>(&sB[r][c4 * 4]) = v;
    }
    __syncthreads();

    float acc[4][4];
    #pragma unroll
    for (int i = 0; i < 4; i++)
        #pragma unroll
        for (int j = 0; j < 4; j++) acc[i][j] = 0.0f;

    const int ty4 = threadIdx.y * 4;
    const int tx4 = threadIdx.x * 4;

    #pragma unroll 4
    for (int k = 0; k < IN_F; k++) {
        float a0 = sA[ty4 + 0][k];
        float a1 = sA[ty4 + 1][k];
        float a2 = sA[ty4 + 2][k];
        float a3 = sA[ty4 + 3][k];
        float4 b = *reinterpret_cast<const float4*>(&sB[k][tx4]);
        acc[0][0] += a0 * b.x; acc[0][1] += a0 * b.y; acc[0][2] += a0 * b.z; acc[0][3] += a0 * b.w;
        acc[1][0] += a1 * b.x; acc[1][1] += a1 * b.y; acc[1][2] += a1 * b.z; acc[1][3] += a1 * b.w;
        acc[2][0] += a2 * b.x; acc[2][1] += a2 * b.y; acc[2][2] += a2 * b.z; acc[2][3] += a2 * b.w;
        acc[3][0] += a3 * b.x; acc[3][1] += a3 * b.y; acc[3][2] += a3 * b.z; acc[3][3] += a3 * b.w;
    }

    float4 bi = *reinterpret_cast<const float4*>(&bias[tx4]);

    #pragma unroll
    for (int i = 0; i < 4; i++) {
        int gr = rowBase + ty4 + i;
        if (gr >= n) break;
        float d = g_deg[gr];
        float norm = 1.0f / fmaxf(d, 1.0f);
        float4 fr = make_float4(acc[i][0], acc[i][1], acc[i][2], acc[i][3]);
        float4 o  = make_float4(fr.x + bi.x, fr.y + bi.y, fr.z + bi.z, fr.w + bi.w);
        reinterpret_cast<float4*>(out)[(size_t)gr * (OUT_F / 4) + (tx4 >> 2)] = o;

        __nv_bfloat162 p0 = __floats2bfloat162_rn(fr.x * norm, fr.y * norm);
        __nv_bfloat162 p1 = __floats2bfloat162_rn(fr.z * norm, fr.w * norm);
        uint2 u;
        u.x = *reinterpret_cast<unsigned*>(&p0);
        u.y = *reinterpret_cast<unsigned*>(&p1);
        *reinterpret_cast<uint2*>(&g_h16[(size_t)gr * (OUT_F / 2) + (tx4 >> 1)]) = u;
    }
}

// ---------------------------------------------------------------------------
// K6: pull-gather. 8 threads per dst node; uint4 (16B) per lane; unroll x4
// ---------------------------------------------------------------------------
__global__ __launch_bounds__(256) void gather_kernel(
    float* __restrict__ out,
    const float* __restrict__ edge_weight,
    int n)
{
    __shared__ float s_wl[8];
    if (threadIdx.x < 8) {
        float w = edge_weight[threadIdx.x] * ALPHAF;
        s_wl[threadIdx.x] = (w > 0.0f) ? w : 0.01f * w;
    }
    __syncthreads();

    int node = blockIdx.x * 32 + (threadIdx.x >> 3);
    int lane = threadIdx.x & 7;
    if (node >= n) return;

    const int st = g_rowstart[node];
    const int cnt = g_cnt[node];

    float acc[8];
    #pragma unroll
    for (int j = 0; j < 8; j++) acc[j] = 0.0f;

    const uint4* __restrict__ hp = reinterpret_cast<const uint4*>(g_h16);

    int i = 0;
    for (; i + 4 <= cnt; i += 4) {
        unsigned e0 = g_epack[st + i + 0];
        unsigned e1 = g_epack[st + i + 1];
        unsigned e2 = g_epack[st + i + 2];
        unsigned e3 = g_epack[st + i + 3];
        uint4 h0 = hp[(size_t)(e0 & 0x1FFFFu) * 8 + lane];
        uint4 h1 = hp[(size_t)(e1 & 0x1FFFFu) * 8 + lane];
        uint4 h2 = hp[(size_t)(e2 & 0x1FFFFu) * 8 + lane];
        uint4 h3 = hp[(size_t)(e3 & 0x1FFFFu) * 8 + lane];
        float w0 = s_wl[e0 >> 17];
        float w1 = s_wl[e1 >> 17];
        float w2 = s_wl[e2 >> 17];
        float w3 = s_wl[e3 >> 17];
        const __nv_bfloat162* b0 = reinterpret_cast<const __nv_bfloat162*>(&h0);
        const __nv_bfloat162* b1 = reinterpret_cast<const __nv_bfloat162*>(&h1);
        const __nv_bfloat162* b2 = reinterpret_cast<const __nv_bfloat162*>(&h2);
        const __nv_bfloat162* b3 = reinterpret_cast<const __nv_bfloat162*>(&h3);
        #pragma unroll
        for (int j = 0; j < 4; j++) {
            float2 f0 = __bfloat1622float2(b0[j]);
            float2 f1 = __bfloat1622float2(b1[j]);
            float2 f2 = __bfloat1622float2(b2[j]);
            float2 f3 = __bfloat1622float2(b3[j]);
            acc[2 * j + 0] += f0.x * w0 + f1.x * w1 + f2.x * w2 + f3.x * w3;
            acc[2 * j + 1] += f0.y * w0 + f1.y * w1 + f2.y * w2 + f3.y * w3;
        }
    }
    for (; i < cnt; i++) {
        unsigned e0 = g_epack[st + i];
        uint4 h0 = hp[(size_t)(e0 & 0x1FFFFu) * 8 + lane];
        float w0 = s_wl[e0 >> 17];
        const __nv_bfloat162* b0 = reinterpret_cast<const __nv_bfloat162*>(&h0);
        #pragma unroll
        for (int j = 0; j < 4; j++) {
            float2 f0 = __bfloat1622float2(b0[j]);
            acc[2 * j + 0] += f0.x * w0;
            acc[2 * j + 1] += f0.y * w0;
        }
    }

    float4* op = reinterpret_cast<float4*>(out + (size_t)node * OUT_F + lane * 8);
    float4 a = op[0];
    float4 b = op[1];
    a.x += acc[0]; a.y += acc[1]; a.z += acc[2]; a.w += acc[3];
    b.x += acc[4]; b.y += acc[5]; b.z += acc[6]; b.w += acc[7];
    op[0] = a;
    op[1] = b;
}

// ---------------------------------------------------------------------------
// Launch
// ---------------------------------------------------------------------------
extern "C" void kernel_launch(void* const* d_in, const int* in_sizes, int n_in,
                              void* d_out, int out_size) {
    const float* feat        = (const float*)d_in[0];
    const float* edge_weight = (const float*)d_in[1];
    const float* weight      = (const float*)d_in[2];
    const float* bias        = (const float*)d_in[3];
    const int*   src         = (const int*)d_in[4];
    const int*   dst         = (const int*)d_in[5];
    const int*   efeat       = (const int*)d_in[6];
    float* out = (float*)d_out;

    int n = in_sizes[0] / IN_F;
    int E = in_sizes[4];
    int nb = (n + 2047) / 2048;
    int ne2 = (E + 1) / 2;

    zero_kernel<<<(n + 255) / 256, 256>>>(n);
    hist_kernel<<<(ne2 + 255) / 256, 256>>>(dst, efeat, edge_weight, E);
    scan_kernel<<<nb, 256>>>(n);
    scatter_kernel<<<(ne2 + 255) / 256, 256>>>(src, dst, efeat, E);

    dim3 gblk(16, 16);
    gemm_kernel<<<(n + 63) / 64, gblk>>>(feat, weight, bias, out, n);

    gather_kernel<<<(n + 31) / 32, 256>>>(out, edge_weight, n);
}

// round 15
// speedup vs baseline: 1.1514x; 1.0472x over previous
#include <cuda_runtime.h>
#include <cuda_bf16.h>
#include <cstdint>

#define IN_F 128
#define OUT_F 64
#define MAX_N 100000
#define MAX_E 1600000
#define ALPHAF 10.0f

// Scratch (allocation-free rule: __device__ globals)
__device__ int      g_cnt[MAX_N];        // per-dst in-degree counts
__device__ int      g_rowstart[MAX_N];   // CSR row offsets
__device__ int      g_cursor[MAX_N];     // scatter cursors
__device__ float    g_deg[MAX_N];        // sum of incoming edge weights
__device__ unsigned g_h16[(size_t)MAX_N * (OUT_F / 2)];  // h rows in bf16x2 words
__device__ unsigned g_epack[MAX_E];      // packed edge: src | (etype<<17)
// scan state: per-block aggregate + publish flag
__device__ volatile int g_scanflag[64];
__device__ volatile int g_scanagg[64];

// ---------------------------------------------------------------------------
// K1: zero counters + deg + scan flags
// ---------------------------------------------------------------------------
__global__ void zero_kernel(int n) {
    int i = blockIdx.x * blockDim.x + threadIdx.x;
    if (i < n) { g_cnt[i] = 0; g_deg[i] = 0.0f; }
    if (blockIdx.x == 0 && threadIdx.x < 64) g_scanflag[threadIdx.x] = 0;
}

// ---------------------------------------------------------------------------
// K2: histogram of dst + fused deg accumulation. 2 edges/thread (MLP=2).
// Both atomicAdd returns UNUSED -> REDG (no round-trip).
// ---------------------------------------------------------------------------
__global__ void hist_kernel(const int* __restrict__ dst,
                            const int* __restrict__ efeat,
                            const float* __restrict__ edge_weight,
                            int E) {
    int e = (blockIdx.x * blockDim.x + threadIdx.x) * 2;
    if (e + 1 < E) {
        int2 d2 = *reinterpret_cast<const int2*>(dst + e);
        int2 t2 = *reinterpret_cast<const int2*>(efeat + e);
        float w0 = __ldg(&edge_weight[t2.x - 1]) * ALPHAF;
        float w1 = __ldg(&edge_weight[t2.y - 1]) * ALPHAF;
        w0 = (w0 > 0.0f) ? w0 : 0.01f * w0;
        w1 = (w1 > 0.0f) ? w1 : 0.01f * w1;
        atomicAdd(&g_cnt[d2.x], 1);
        atomicAdd(&g_cnt[d2.y], 1);
        atomicAdd(&g_deg[d2.x], w0);
        atomicAdd(&g_deg[d2.y], w1);
    } else if (e < E) {
        int d = dst[e];
        float w = __ldg(&edge_weight[efeat[e] - 1]) * ALPHAF;
        w = (w > 0.0f) ? w : 0.01f * w;
        atomicAdd(&g_cnt[d], 1);
        atomicAdd(&g_deg[d], w);
    }
}

// ---------------------------------------------------------------------------
// K3: single-pass exclusive scan (parallel aggregate lookback)
// ---------------------------------------------------------------------------
__global__ __launch_bounds__(256) void scan_kernel(int n) {
    __shared__ int s[256];
    __shared__ int s_off;
    const int tid = threadIdx.x;
    const int b = blockIdx.x;
    const int base = b * 2048 + tid * 8;

    int v[8];
    int tsum = 0;
    #pragma unroll
    for (int j = 0; j < 8; j++) {
        int idx = base + j;
        int c = (idx < n) ? g_cnt[idx] : 0;
        v[j] = tsum;
        tsum += c;
    }
    s[tid] = tsum;
    __syncthreads();
    #pragma unroll
    for (int off = 1; off < 256; off <<= 1) {
        int t = 0;
        if (tid >= off) t = s[tid - off];
        __syncthreads();
        if (tid >= off) s[tid] += t;
        __syncthreads();
    }
    int texcl = s[tid] - tsum;
    int total = s[255];

    if (tid == 0) {
        s_off = 0;
        g_scanagg[b] = total;
        __threadfence();
        g_scanflag[b] = 1;
    }
    __syncthreads();

    if (tid < 32 && b > 0) {
        int run = 0;
        for (int base2 = 0; base2 < b; base2 += 32) {
            int p = base2 + tid;
            int val = 0;
            if (p < b) {
                while (g_scanflag[p] == 0) { }
                __threadfence();
                val = g_scanagg[p];
            }
            #pragma unroll
            for (int o = 16; o; o >>= 1)
                val += __shfl_down_sync(0xffffffffu, val, o);
            if (tid == 0) run += val;
        }
        if (tid == 0) s_off = run;
    }
    __syncthreads();
    int off = s_off;

    #pragma unroll
    for (int j = 0; j < 8; j++) {
        int idx = base + j;
        if (idx < n) {
            int r = off + texcl + v[j];
            g_rowstart[idx] = r;
            g_cursor[idx] = r;
        }
    }
}

// ---------------------------------------------------------------------------
// K4: scatter packed edges into CSR slots (cursor atomic). 2 edges/thread.
// ---------------------------------------------------------------------------
__global__ void scatter_kernel(const int* __restrict__ src,
                               const int* __restrict__ dst,
                               const int* __restrict__ efeat,
                               int E) {
    int e = (blockIdx.x * blockDim.x + threadIdx.x) * 2;
    if (e + 1 < E) {
        int2 s2 = *reinterpret_cast<const int2*>(src + e);
        int2 d2 = *reinterpret_cast<const int2*>(dst + e);
        int2 t2 = *reinterpret_cast<const int2*>(efeat + e);
        int p0 = atomicAdd(&g_cursor[d2.x], 1);
        int p1 = atomicAdd(&g_cursor[d2.y], 1);
        g_epack[p0] = (unsigned)s2.x | ((unsigned)(t2.x - 1) << 17);
        g_epack[p1] = (unsigned)s2.y | ((unsigned)(t2.y - 1) << 17);
    } else if (e < E) {
        int d = dst[e];
        int p = atomicAdd(&g_cursor[d], 1);
        g_epack[p] = (unsigned)src[e] | ((unsigned)(efeat[e] - 1) << 17);
    }
}

// ---------------------------------------------------------------------------
// K5: TF32 tensor-core GEMM with 3xTF32 compensation (~fp32 accuracy).
// fr = feat @ weight ; out = fr + bias ; g_h16 = bf16(fr/max(deg,1))
// Block: 64 rows x 64 cols, 8 warps of 16x32, K=128 in smem.
// ---------------------------------------------------------------------------
#define SA_STRIDE 132   // 64 rows
#define SB_STRIDE 72    // 128 rows

__device__ __forceinline__ unsigned f2tf32(float f) {
    unsigned r;
    asm("cvt.rna.tf32.f32 %0, %1;" : "=r"(r) : "f"(f));
    return r;
}

#define MMA_TF32(c, a0, a1, a2, a3, b0, b1)                                   \
    asm volatile("mma.sync.aligned.m16n8k8.row.col.f32.tf32.tf32.f32 "        \
                 "{%0,%1,%2,%3}, {%4,%5,%6,%7}, {%8,%9}, {%0,%1,%2,%3};"      \
                 : "+f"((c)[0]), "+f"((c)[1]), "+f"((c)[2]), "+f"((c)[3])     \
                 : "r"(a0), "r"(a1), "r"(a2), "r"(a3), "r"(b0), "r"(b1))

__global__ __launch_bounds__(256) void gemm_kernel(
    const float* __restrict__ feat,
    const float* __restrict__ weight,
    const float* __restrict__ bias,
    float* __restrict__ out,
    int n)
{
    __shared__ float sA[64 * SA_STRIDE];
    __shared__ float sB[IN_F * SB_STRIDE];

    const int tid = threadIdx.x;
    const int rowBase = blockIdx.x * 64;

    // Load A tile (64x128 f32) — float4, padded stride keeps alignment (132%4==0)
    #pragma unroll
    for (int it = 0; it < 8; it++) {
        int idx = tid + it * 256;
        int r = idx >> 5;
        int c4 = idx & 31;
        float4 v = make_float4(0.f, 0.f, 0.f, 0.f);
        int gr = rowBase + r;
        if (gr < n)
            v = reinterpret_cast<const float4*>(feat)[(size_t)gr * (IN_F / 4) + c4];
        *reinterpret_cast<float4*>(&sA[r * SA_STRIDE + c4 * 4]) = v;
    }
    // Load B tile (128x64 f32)
    #pragma unroll
    for (int it = 0; it < 8; it++) {
        int idx = tid + it * 256;
        int r = idx >> 4;
        int c4 = idx & 15;
        float4 v = reinterpret_cast<const float4*>(weight)[(size_t)r * (OUT_F / 4) + c4];
        *reinterpret_cast<float4*>(&sB[r * SB_STRIDE + c4 * 4]) = v;
    }
    __syncthreads();

    const int wid = tid >> 5;
    const int lane = tid & 31;
    const int g = lane >> 2;          // groupID
    const int t = lane & 3;           // threadID_in_group
    const int m0 = (wid & 3) * 16;    // warp M offset
    const int n0 = (wid >> 2) * 32;   // warp N offset

    float c[4][4];
    #pragma unroll
    for (int nt = 0; nt < 4; nt++)
        #pragma unroll
        for (int j = 0; j < 4; j++) c[nt][j] = 0.0f;

    #pragma unroll
    for (int ks = 0; ks < IN_F / 8; ks++) {
        int k0 = ks * 8;
        // A fragments (row-major m16k8)
        float af0 = sA[(m0 + g)     * SA_STRIDE + k0 + t];
        float af1 = sA[(m0 + g + 8) * SA_STRIDE + k0 + t];
        float af2 = sA[(m0 + g)     * SA_STRIDE + k0 + t + 4];
        float af3 = sA[(m0 + g + 8) * SA_STRIDE + k0 + t + 4];
        unsigned ah0 = f2tf32(af0), ah1 = f2tf32(af1), ah2 = f2tf32(af2), ah3 = f2tf32(af3);
        unsigned al0 = f2tf32(af0 - __uint_as_float(ah0));
        unsigned al1 = f2tf32(af1 - __uint_as_float(ah1));
        unsigned al2 = f2tf32(af2 - __uint_as_float(ah2));
        unsigned al3 = f2tf32(af3 - __uint_as_float(ah3));

        #pragma unroll
        for (int nt = 0; nt < 4; nt++) {
            int nc = n0 + nt * 8 + g;
            float bf0 = sB[(k0 + t)     * SB_STRIDE + nc];
            float bf1 = sB[(k0 + t + 4) * SB_STRIDE + nc];
            unsigned bh0 = f2tf32(bf0), bh1 = f2tf32(bf1);
            unsigned bl0 = f2tf32(bf0 - __uint_as_float(bh0));
            unsigned bl1 = f2tf32(bf1 - __uint_as_float(bh1));
            MMA_TF32(c[nt], ah0, ah1, ah2, ah3, bh0, bh1);   // hi*hi
            MMA_TF32(c[nt], al0, al1, al2, al3, bh0, bh1);   // lo*hi
            MMA_TF32(c[nt], ah0, ah1, ah2, ah3, bl0, bl1);   // hi*lo
        }
    }

    // Epilogue: c[nt] = {(g,2t),(g,2t+1),(g+8,2t),(g+8,2t+1)} at col n0+nt*8
    #pragma unroll
    for (int half = 0; half < 2; half++) {
        int gr = rowBase + m0 + g + half * 8;
        if (gr < n) {
            float d = g_deg[gr];
            float norm = 1.0f / fmaxf(d, 1.0f);
            #pragma unroll
            for (int nt = 0; nt < 4; nt++) {
                int col = n0 + nt * 8 + 2 * t;
                float cx = c[nt][half * 2 + 0];
                float cy = c[nt][half * 2 + 1];
                float2 bi = *reinterpret_cast<const float2*>(bias + col);
                float2 o = make_float2(cx + bi.x, cy + bi.y);
                *reinterpret_cast<float2*>(out + (size_t)gr * OUT_F + col) = o;
                __nv_bfloat162 p = __floats2bfloat162_rn(cx * norm, cy * norm);
                g_h16[(size_t)gr * (OUT_F / 2) + (col >> 1)] = *reinterpret_cast<unsigned*>(&p);
            }
        }
    }
}

// ---------------------------------------------------------------------------
// K6: pull-gather. 8 threads per dst node; uint4 (16B) per lane; unroll x4
// ---------------------------------------------------------------------------
__global__ __launch_bounds__(256) void gather_kernel(
    float* __restrict__ out,
    const float* __restrict__ edge_weight,
    int n)
{
    __shared__ float s_wl[8];
    if (threadIdx.x < 8) {
        float w = edge_weight[threadIdx.x] * ALPHAF;
        s_wl[threadIdx.x] = (w > 0.0f) ? w : 0.01f * w;
    }
    __syncthreads();

    int node = blockIdx.x * 32 + (threadIdx.x >> 3);
    int lane = threadIdx.x & 7;
    if (node >= n) return;

    const int st = g_rowstart[node];
    const int cnt = g_cnt[node];

    float acc[8];
    #pragma unroll
    for (int j = 0; j < 8; j++) acc[j] = 0.0f;

    const uint4* __restrict__ hp = reinterpret_cast<const uint4*>(g_h16);

    int i = 0;
    for (; i + 4 <= cnt; i += 4) {
        unsigned e0 = g_epack[st + i + 0];
        unsigned e1 = g_epack[st + i + 1];
        unsigned e2 = g_epack[st + i + 2];
        unsigned e3 = g_epack[st + i + 3];
        uint4 h0 = hp[(size_t)(e0 & 0x1FFFFu) * 8 + lane];
        uint4 h1 = hp[(size_t)(e1 & 0x1FFFFu) * 8 + lane];
        uint4 h2 = hp[(size_t)(e2 & 0x1FFFFu) * 8 + lane];
        uint4 h3 = hp[(size_t)(e3 & 0x1FFFFu) * 8 + lane];
        float w0 = s_wl[e0 >> 17];
        float w1 = s_wl[e1 >> 17];
        float w2 = s_wl[e2 >> 17];
        float w3 = s_wl[e3 >> 17];
        const __nv_bfloat162* b0 = reinterpret_cast<const __nv_bfloat162*>(&h0);
        const __nv_bfloat162* b1 = reinterpret_cast<const __nv_bfloat162*>(&h1);
        const __nv_bfloat162* b2 = reinterpret_cast<const __nv_bfloat162*>(&h2);
        const __nv_bfloat162* b3 = reinterpret_cast<const __nv_bfloat162*>(&h3);
        #pragma unroll
        for (int j = 0; j < 4; j++) {
            float2 f0 = __bfloat1622float2(b0[j]);
            float2 f1 = __bfloat1622float2(b1[j]);
            float2 f2 = __bfloat1622float2(b2[j]);
            float2 f3 = __bfloat1622float2(b3[j]);
            acc[2 * j + 0] += f0.x * w0 + f1.x * w1 + f2.x * w2 + f3.x * w3;
            acc[2 * j + 1] += f0.y * w0 + f1.y * w1 + f2.y * w2 + f3.y * w3;
        }
    }
    for (; i < cnt; i++) {
        unsigned e0 = g_epack[st + i];
        uint4 h0 = hp[(size_t)(e0 & 0x1FFFFu) * 8 + lane];
        float w0 = s_wl[e0 >> 17];
        const __nv_bfloat162* b0 = reinterpret_cast<const __nv_bfloat162*>(&h0);
        #pragma unroll
        for (int j = 0; j < 4; j++) {
            float2 f0 = __bfloat1622float2(b0[j]);
            acc[2 * j + 0] += f0.x * w0;
            acc[2 * j + 1] += f0.y * w0;
        }
    }

    float4* op = reinterpret_cast<float4*>(out + (size_t)node * OUT_F + lane * 8);
    float4 a = op[0];
    float4 b = op[1];
    a.x += acc[0]; a.y += acc[1]; a.z += acc[2]; a.w += acc[3];
    b.x += acc[4]; b.y += acc[5]; b.z += acc[6]; b.w += acc[7];
    op[0] = a;
    op[1] = b;
}

// ---------------------------------------------------------------------------
// Launch
// ---------------------------------------------------------------------------
extern "C" void kernel_launch(void* const* d_in, const int* in_sizes, int n_in,
                              void* d_out, int out_size) {
    const float* feat        = (const float*)d_in[0];
    const float* edge_weight = (const float*)d_in[1];
    const float* weight      = (const float*)d_in[2];
    const float* bias        = (const float*)d_in[3];
    const int*   src         = (const int*)d_in[4];
    const int*   dst         = (const int*)d_in[5];
    const int*   efeat       = (const int*)d_in[6];
    float* out = (float*)d_out;

    int n = in_sizes[0] / IN_F;
    int E = in_sizes[4];
    int nb = (n + 2047) / 2048;
    int ne2 = (E + 1) / 2;

    zero_kernel<<<(n + 255) / 256, 256>>>(n);
    hist_kernel<<<(ne2 + 255) / 256, 256>>>(dst, efeat, edge_weight, E);
    scan_kernel<<<nb, 256>>>(n);
    scatter_kernel<<<(ne2 + 255) / 256, 256>>>(src, dst, efeat, E);

    gemm_kernel<<<(n + 63) / 64, 256>>>(feat, weight, bias, out, n);

    gather_kernel<<<(n + 31) / 32, 256>>>(out, edge_weight, n);
}